// round 9
// baseline (speedup 1.0000x reference)
#include <cuda_runtime.h>

#define HIDDEN 32
#define FF 40
#define TSTEPS 512
#define BATCH 16384
#define EPB 128           /* elements per block; each thread handles 2 */
#define THREADS 512       /* 16 warps = 2 roles x 4 col-groups x 2 elem-groups */

typedef unsigned long long u64;

__device__ __forceinline__ u64 pk(float a, float b) {
    u64 r; asm("mov.b64 %0,{%1,%2};" : "=l"(r) : "f"(a), "f"(b)); return r;
}
__device__ __forceinline__ void upk(u64 v, float& a, float& b) {
    asm("mov.b64 {%0,%1},%2;" : "=f"(a), "=f"(b) : "l"(v));
}
__device__ __forceinline__ u64 f2fma(u64 a, u64 b, u64 c) {
    u64 d; asm("fma.rn.f32x2 %0,%1,%2,%3;" : "=l"(d) : "l"(a), "l"(b), "l"(c)); return d;
}
// sigmoid via ex2/rcp approx (~1e-6 rel; proven rel_err ~2.5e-7 across rounds)
__device__ __forceinline__ float sigm(float x) {
    float e, r;
    asm("ex2.approx.ftz.f32 %0,%1;" : "=f"(e) : "f"(x * -1.4426950408889634f));
    asm("rcp.approx.ftz.f32 %0,%1;" : "=f"(r) : "f"(1.0f + e));
    return r;
}

// Dynamic-smem layout (bytes from base; all u64 regions 8B-aligned)
#define OFF_W1HH 0            /* 33*40 floats = 5280  */
#define OFF_W1HO 5280
#define OFF_W2HH 10560        /* 40*32 floats = 5120  */
#define OFF_W2HO 15680        /* 40 floats            */
#define OFF_B1HH 15840
#define OFF_B1HO 16000
#define OFF_B2HH 16160        /* 32 floats -> 16288   */
#define OFF_HBUF 16288        /* u64[16*EPB] = 16384  */
#define OFF_SST  32672        /* u64[20*EPB] = 20480  */
#define OFF_OBUF 53152        /* float[3*EPB] = 1536  */
#define SMEM_TOTAL 54688

__global__ void __launch_bounds__(THREADS, 1) rnn_w16_kernel(
    const float* __restrict__ inp,
    const float* __restrict__ W1hh, const float* __restrict__ b1hh,
    const float* __restrict__ W2hh, const float* __restrict__ b2hh,
    const float* __restrict__ W1ho, const float* __restrict__ b1ho,
    const float* __restrict__ W2ho, const float* __restrict__ b2ho,
    float* __restrict__ out)
{
    extern __shared__ __align__(16) char smem[];
    float* sW1hh = (float*)(smem + OFF_W1HH);
    float* sW1ho = (float*)(smem + OFF_W1HO);
    float* sW2hh = (float*)(smem + OFF_W2HH);
    float* sW2ho = (float*)(smem + OFF_W2HO);
    float* sb1hh = (float*)(smem + OFF_B1HH);
    float* sb1ho = (float*)(smem + OFF_B1HO);
    float* sb2hh = (float*)(smem + OFF_B2HH);
    u64*   hbuf  = (u64*)  (smem + OFF_HBUF);   // packed h pairs, single buffer
    u64*   sst   = (u64*)  (smem + OFF_SST);    // packed sigmoid(z_hh) pairs
    float* obuf  = (float*)(smem + OFF_OBUF);   // ho partial dots, ch 0..2

    const int tid = threadIdx.x;
    for (int i = tid; i < 33 * FF; i += THREADS) { sW1hh[i] = W1hh[i]; sW1ho[i] = W1ho[i]; }
    for (int i = tid; i < FF * HIDDEN; i += THREADS) sW2hh[i] = W2hh[i];
    if (tid < FF) { sW2ho[tid] = W2ho[tid]; sb1hh[tid] = b1hh[tid]; sb1ho[tid] = b1ho[tid]; }
    if (tid < HIDDEN) sb2hh[tid] = b2hh[tid];
    for (int i = tid; i < 16 * EPB; i += THREADS) hbuf[i] = 0ull;   // h0 = 0
    const float bias_o = b2ho[0];
    __syncthreads();

    const int lane = tid & 31;
    const int wid  = tid >> 5;          // 0..15
    const int role = wid >> 3;          // 0 = hh, 1 = ho
    const int sub  = wid & 7;
    const int ch   = sub >> 1;          // column group: j-pairs [5ch, 5ch+5)
    const int eg   = sub & 1;           // element group: [64eg, 64eg+64)
    const int w8   = role * 4 + ch;     // layer-2 slice id (0..7) within eg
    const int e0i  = eg * 64 + lane;
    const int e1i  = e0i + 32;

    const size_t ebase = (size_t)blockIdx.x * EPB;
    const float* __restrict__ ip0 = inp + (ebase + e0i) * TSTEPS;
    const float* __restrict__ ip1 = inp + (ebase + e1i) * TSTEPS;
    float* __restrict__ op0 = out + (ebase + e0i) * TSTEPS;
    float* __restrict__ op1 = out + (ebase + e1i) * TSTEPS;

    // Role-selected layer-1 pointers: one GEMM-loop body serves both roles.
    const float* __restrict__ W1 = role ? sW1ho : sW1hh;
    const u64*  __restrict__ B1  = (const u64*)(role ? sb1ho : sb1hh) + ch * 5;
    const bool is_comb = (role == 1) && (ch == 3);   // output combiner warp

    float u0 = ip0[0], u1 = ip1[0];

    #pragma unroll 1
    for (int t = 0; t < TSTEPS; t++) {
        float u0n = ip0[(t + 1) & (TSTEPS - 1)];
        float u1n = ip1[(t + 1) & (TSTEPS - 1)];

        // ===== phase A: layer 1, this warp's 5 j-pairs, 2 elements =====
        u64 z0[5], z1[5];
        #pragma unroll
        for (int jp = 0; jp < 5; jp++) { u64 b = B1[jp]; z0[jp] = b; z1[jp] = b; }

        #pragma unroll 1
        for (int p = 0; p < 16; p++) {
            float a0, b0; upk(hbuf[p * EPB + e0i], a0, b0);
            float a1, b1; upk(hbuf[p * EPB + e1i], a1, b1);
            u64 ca = pk(a0, a0), cb = pk(a1, a1);
            const u64* w = (const u64*)(W1 + (2 * p) * FF) + ch * 5;
            #pragma unroll
            for (int jp = 0; jp < 5; jp++) {
                u64 W = w[jp];
                z0[jp] = f2fma(ca, W, z0[jp]);
                z1[jp] = f2fma(cb, W, z1[jp]);
            }
            u64 da = pk(b0, b0), db = pk(b1, b1);
            const u64* w2 = (const u64*)(W1 + (2 * p + 1) * FF) + ch * 5;
            #pragma unroll
            for (int jp = 0; jp < 5; jp++) {
                u64 W = w2[jp];
                z0[jp] = f2fma(da, W, z0[jp]);
                z1[jp] = f2fma(db, W, z1[jp]);
            }
        }
        {   // input row 32
            u64 ca = pk(u0, u0), cb = pk(u1, u1);
            const u64* w = (const u64*)(W1 + 32 * FF) + ch * 5;
            #pragma unroll
            for (int jp = 0; jp < 5; jp++) {
                u64 W = w[jp];
                z0[jp] = f2fma(ca, W, z0[jp]);
                z1[jp] = f2fma(cb, W, z1[jp]);
            }
        }

        float part0 = 0.0f, part1 = 0.0f;
        if (role == 0) {
            // sigmoid -> sst pairs [5ch, 5ch+5)
            #pragma unroll
            for (int jp = 0; jp < 5; jp++) {
                float a, b; upk(z0[jp], a, b);
                sst[(ch * 5 + jp) * EPB + e0i] = pk(sigm(a), sigm(b));
                float c, d; upk(z1[jp], c, d);
                sst[(ch * 5 + jp) * EPB + e1i] = pk(sigm(c), sigm(d));
            }
        } else {
            // partial output dot over this warp's 5 pairs
            u64 acc0 = 0ull, acc1 = 0ull;
            const u64* wo = (const u64*)sW2ho + ch * 5;
            #pragma unroll
            for (int jp = 0; jp < 5; jp++) {
                u64 W = wo[jp];
                float a, b; upk(z0[jp], a, b);
                acc0 = f2fma(pk(sigm(a), sigm(b)), W, acc0);
                float c, d; upk(z1[jp], c, d);
                acc1 = f2fma(pk(sigm(c), sigm(d)), W, acc1);
            }
            float a, b; upk(acc0, a, b); part0 = a + b;
            float c, d; upk(acc1, c, d); part1 = c + d;
            if (ch < 3) { obuf[ch * EPB + e0i] = part0; obuf[ch * EPB + e1i] = part1; }
        }

        __syncthreads();   // sst/obuf published; all h reads complete

        // combiner writes out[t] (uses h_{t-1}: matches reference)
        if (is_comb) {
            op0[t] = obuf[e0i] + obuf[EPB + e0i] + obuf[2 * EPB + e0i] + part0 + bias_o;
            op1[t] = obuf[e1i] + obuf[EPB + e1i] + obuf[2 * EPB + e1i] + part1 + bias_o;
        }

        // ===== phase C: layer 2, pairs [2*w8, 2*w8+2), 2 elements =====
        {
            u64 hn0[2], hn1[2];
            const u64* b2 = (const u64*)sb2hh + 2 * w8;
            #pragma unroll
            for (int q = 0; q < 2; q++) { u64 b = b2[q]; hn0[q] = b; hn1[q] = b; }

            #pragma unroll 1
            for (int jq = 0; jq < 20; jq++) {
                float s00, s01; upk(sst[jq * EPB + e0i], s00, s01);
                float s10, s11; upk(sst[jq * EPB + e1i], s10, s11);
                u64 p00 = pk(s00, s00), p10 = pk(s10, s10);
                const u64* w0 = (const u64*)(sW2hh + (2 * jq) * HIDDEN) + 2 * w8;
                #pragma unroll
                for (int q = 0; q < 2; q++) {
                    u64 W = w0[q];
                    hn0[q] = f2fma(p00, W, hn0[q]);
                    hn1[q] = f2fma(p10, W, hn1[q]);
                }
                u64 p01 = pk(s01, s01), p11 = pk(s11, s11);
                const u64* w1 = (const u64*)(sW2hh + (2 * jq + 1) * HIDDEN) + 2 * w8;
                #pragma unroll
                for (int q = 0; q < 2; q++) {
                    u64 W = w1[q];
                    hn0[q] = f2fma(p01, W, hn0[q]);
                    hn1[q] = f2fma(p11, W, hn1[q]);
                }
            }
            #pragma unroll
            for (int q = 0; q < 2; q++) {
                hbuf[(2 * w8 + q) * EPB + e0i] = hn0[q];
                hbuf[(2 * w8 + q) * EPB + e1i] = hn1[q];
            }
        }

        __syncthreads();   // h_t complete; sst/obuf reusable next step

        u0 = u0n; u1 = u1n;
    }
}

extern "C" void kernel_launch(void* const* d_in, const int* in_sizes, int n_in,
                              void* d_out, int out_size) {
    const float* inp  = (const float*)d_in[0];
    const float* W1hh = (const float*)d_in[1];
    const float* b1hh = (const float*)d_in[2];
    const float* W2hh = (const float*)d_in[3];
    const float* b2hh = (const float*)d_in[4];
    const float* W1ho = (const float*)d_in[5];
    const float* b1ho = (const float*)d_in[6];
    const float* W2ho = (const float*)d_in[7];
    const float* b2ho = (const float*)d_in[8];
    float* out = (float*)d_out;

    // Idempotent, capture-safe (no allocation, no sync, no stream op).
    cudaFuncSetAttribute(rnn_w16_kernel,
                         cudaFuncAttributeMaxDynamicSharedMemorySize, SMEM_TOTAL);

    dim3 grid(BATCH / EPB);   // 128 blocks x 512 threads: 16 warps on each of 128 SMs
    dim3 block(THREADS);
    rnn_w16_kernel<<<grid, block, SMEM_TOTAL>>>(inp, W1hh, b1hh, W2hh, b2hh,
                                                W1ho, b1ho, W2ho, b2ho, out);
}